// round 8
// baseline (speedup 1.0000x reference)
#include <cuda_runtime.h>
#include <cstdint>

#define M_DIM 512
#define K_DIM 256
#define O_DIM 256
#define RBLK 128          /* reduce blocks */
#define TP   260          /* padded row stride: 260 mod 32 == 4 -> conflict-free LDS.128 */

#define BIGF  12582912.0f          /* 1.5 * 2^23 */
#define BIGU  0x4B400000u
#define THETA 0.0009765625f        /* 2^-10 */
#define EPSB  0.000244140625f      /* 2^-12 */

// ---------------- device scratch (no allocations allowed) ----------------
__device__ float2 g_bmax2[RBLK];   // per-block (max|x|, max(|W|,|b|))

// ---------------- helpers ----------------
__device__ __forceinline__ float san(float v) {
    if (isnan(v)) return 0.0f;
    if (isinf(v)) return 1.0f;
    return v;
}

// sn = 2^floor(log2(floor(32/mx))); argument of log2 is a positive integer.
__device__ __forceinline__ float calc_sn(float mx) {
    if (mx == 0.0f) mx = 1.0f;
    float r = floorf(32.0f / mx);
    return ldexpf(1.0f, ilogbf(r));
}

// block-level max reduce of (mx, md) over 256 threads; result valid in ALL threads
__device__ __forceinline__ float2 block_max2(float mx, float md) {
    __shared__ float2 s_red[8];
    __shared__ float2 s_out;
    #pragma unroll
    for (int off = 16; off; off >>= 1) {
        mx = fmaxf(mx, __shfl_xor_sync(0xFFFFFFFFu, mx, off));
        md = fmaxf(md, __shfl_xor_sync(0xFFFFFFFFu, md, off));
    }
    if ((threadIdx.x & 31) == 0) s_red[threadIdx.x >> 5] = make_float2(mx, md);
    __syncthreads();
    if (threadIdx.x == 0) {
        float2 r = s_red[0];
        #pragma unroll
        for (int w = 1; w < 8; w++) {
            r.x = fmaxf(r.x, s_red[w].x);
            r.y = fmaxf(r.y, s_red[w].y);
        }
        s_out = r;
    }
    __syncthreads();
    return s_out;
}

// ---------------- pass 1: per-block maxima (no atomics, no reset) ----------------
__global__ __launch_bounds__(256) void reduce_kernel(const float* __restrict__ x,
                                                     const float* __restrict__ W,
                                                     const float* __restrict__ b) {
    float mx = 0.0f, md = 0.0f;
    int t = blockIdx.x * 256 + threadIdx.x;
    const int stride = RBLK * 256;
    for (int i = t; i < M_DIM * K_DIM; i += stride) mx = fmaxf(mx, fabsf(san(x[i])));
    for (int i = t; i < O_DIM * K_DIM; i += stride) md = fmaxf(md, fabsf(san(W[i])));
    md = fmaxf(md, fabsf(san(b[threadIdx.x])));   // 256 threads cover b exactly
    float2 r = block_max2(mx, md);
    if (threadIdx.x == 0) g_bmax2[blockIdx.x] = r;
}

// ---------------- pass 2: fused quantize + LUT-GEMM + epilogue ----------------
// Tile 16m x 16o, FULL K=256 staged once (no k-loop syncs). grid = (16, 32) =
// 512 blocks (~3.5 CTA/SM). 256 threads, 1 output each, 4 k's per LDS.128,
// 4 independent accumulator chains. 2.5 instr/MAC.
__global__ __launch_bounds__(256) void fused_kernel(const float* __restrict__ x,
                                                    const float* __restrict__ W,
                                                    const float* __restrict__ b,
                                                    float* __restrict__ out) {
    __shared__ float s_a[16][TP];   // [m][k], float(trunc(x*sn2)) + 2^-10
    __shared__ float s_u[16][TP];   // [o][k], bb/32 (- 2^-12 if bb<0)
    __shared__ int   s_neg[16];     // per local-o count of bb<0 over full K

    // prologue: finalize global maxima -> sn1, sn2 (all threads)
    float mx = 0.0f, md = 0.0f;
    if (threadIdx.x < RBLK) {
        float2 v = g_bmax2[threadIdx.x];
        mx = v.x; md = v.y;
    }
    float2 r = block_max2(mx, md);
    float sn2 = calc_sn(r.x);
    float sn1 = calc_sn(r.y);

    int m0 = blockIdx.y * 16;
    int o0 = blockIdx.x * 16;
    int row = threadIdx.x >> 4;          // staging row (m for x, o for W), 0..15
    int kg  = (threadIdx.x & 15) << 4;   // staging k-offset, 16 floats each

    // stage + on-the-fly quantize (coalesced LDG.128)
    int negcnt = 0;
    {
        const float4* px = (const float4*)&x[(m0 + row) * K_DIM + kg];
        const float4* pw = (const float4*)&W[(o0 + row) * K_DIM + kg];
        #pragma unroll
        for (int j = 0; j < 4; j++) {
            float4 a4 = px[j];
            float4 w4 = pw[j];
            float av[4] = {a4.x, a4.y, a4.z, a4.w};
            float wv[4] = {w4.x, w4.y, w4.z, w4.w};
            #pragma unroll
            for (int e = 0; e < 4; e++) {
                s_a[row][kg + 4 * j + e] = (float)(int)(san(av[e]) * sn2) + THETA;
                int bb = (int)(san(wv[e]) * sn1);
                float us = (float)bb * (1.0f / 32.0f);
                if (bb < 0) { us -= EPSB; negcnt++; }
                s_u[row][kg + 4 * j + e] = us;
            }
        }
    }
    // per-o negative count: the 16 threads sharing `row` are 16 consecutive lanes
    #pragma unroll
    for (int off = 1; off < 16; off <<= 1)
        negcnt += __shfl_xor_sync(0xFFFFFFFFu, negcnt, off);
    if ((threadIdx.x & 15) == 0) s_neg[row] = negcnt;
    __syncthreads();

    int tx = threadIdx.x & 15;      // o
    int ty = threadIdx.x >> 4;      // m

    unsigned acc0 = 0, acc1 = 0, acc2 = 0, acc3 = 0;

    #pragma unroll 8
    for (int k = 0; k < K_DIM; k += 4) {
        float4 a4 = *reinterpret_cast<const float4*>(&s_a[ty][k]);  // broadcast
        float4 u4 = *reinterpret_cast<const float4*>(&s_u[tx][k]);  // conflict-free
        acc0 += __float_as_uint(__fmaf_rd(a4.x, u4.x, BIGF));
        acc1 += __float_as_uint(__fmaf_rd(a4.y, u4.y, BIGF));
        acc2 += __float_as_uint(__fmaf_rd(a4.z, u4.z, BIGF));
        acc3 += __float_as_uint(__fmaf_rd(a4.w, u4.w, BIGF));
    }

    // epilogue: x9 = (Σacc - K*BIGU mod 2^32) + N_o ; d = trunc(x9/sn2) + cc ;
    // out = d/sn1  (exact pow-2 ops, trunc = C cast)
    const unsigned C = (unsigned)((unsigned)K_DIM * BIGU);
    unsigned acc = acc0 + acc1 + acc2 + acc3;
    int o = o0 + tx;
    int m = m0 + ty;
    int x9 = (int)(acc - C) + s_neg[tx];
    int cc = (int)(san(b[o]) * sn1);
    out[m * O_DIM + o] = (float)((int)((float)x9 / sn2) + cc) / sn1;
}

// ---------------- launch ----------------
extern "C" void kernel_launch(void* const* d_in, const int* in_sizes, int n_in,
                              void* d_out, int out_size) {
    (void)in_sizes; (void)n_in; (void)out_size;
    const float* x = (const float*)d_in[0];
    const float* W = (const float*)d_in[1];
    const float* b = (const float*)d_in[2];
    // d_in[3] (lut) unused: lut[i][j] == floor(i*j/32), reproduced exactly by
    // the FFMA.RD magic-floor + raw-bits accumulation.

    reduce_kernel<<<RBLK, 256>>>(x, W, b);
    dim3 grid(O_DIM / 16, M_DIM / 16);
    fused_kernel<<<grid, 256>>>(x, W, b, (float*)d_out);
}

// round 10
// speedup vs baseline: 1.1955x; 1.1955x over previous
#include <cuda_runtime.h>
#include <cstdint>

#define M_DIM 512
#define K_DIM 256
#define O_DIM 256
#define BK 64
#define KSPLIT 4
#define RBLK 128          /* reduce blocks */

#define BIGF  12582912.0f          /* 1.5 * 2^23 */
#define BIGU  0x4B400000u
#define THETA 0.0009765625f        /* 2^-10 */
#define EPSB  0.000244140625f      /* 2^-12 */

// ---------------- device scratch (no allocations allowed) ----------------
__device__ float2 g_bmax2[RBLK];                  // per-block (max|x|, max(|W|,|b|))
__device__ int    g_part[KSPLIT][M_DIM * O_DIM];  // exact per-chunk partial sums
__device__ unsigned g_cnt[(M_DIM / 32) * (O_DIM / 32)];  // tile arrival counters (=0)

// ---------------- helpers ----------------
__device__ __forceinline__ float san(float v) {
    if (isnan(v)) return 0.0f;
    if (isinf(v)) return 1.0f;
    return v;
}

// sn = 2^floor(log2(floor(32/mx))); argument of log2 is a positive integer.
__device__ __forceinline__ float calc_sn(float mx) {
    if (mx == 0.0f) mx = 1.0f;
    float r = floorf(32.0f / mx);
    return ldexpf(1.0f, ilogbf(r));
}

// block-level max reduce of (mx, md) over 256 threads; result valid in ALL threads
__device__ __forceinline__ float2 block_max2(float mx, float md) {
    __shared__ float2 s_red[8];
    __shared__ float2 s_out;
    #pragma unroll
    for (int off = 16; off; off >>= 1) {
        mx = fmaxf(mx, __shfl_xor_sync(0xFFFFFFFFu, mx, off));
        md = fmaxf(md, __shfl_xor_sync(0xFFFFFFFFu, md, off));
    }
    if ((threadIdx.x & 31) == 0) s_red[threadIdx.x >> 5] = make_float2(mx, md);
    __syncthreads();
    if (threadIdx.x == 0) {
        float2 r = s_red[0];
        #pragma unroll
        for (int w = 1; w < 8; w++) {
            r.x = fmaxf(r.x, s_red[w].x);
            r.y = fmaxf(r.y, s_red[w].y);
        }
        s_out = r;
    }
    __syncthreads();
    return s_out;
}

// ---------------- pass 1: per-block maxima (no atomics, no reset) ----------------
__global__ __launch_bounds__(256) void reduce_kernel(const float* __restrict__ x,
                                                     const float* __restrict__ W,
                                                     const float* __restrict__ b) {
    int t = blockIdx.x * 256 + threadIdx.x;          // 0..32767
    float mx = 0.0f, md = 0.0f;
    float4 a = reinterpret_cast<const float4*>(x)[t];            // covers M*K exactly
    mx = fmaxf(fmaxf(fabsf(san(a.x)), fabsf(san(a.y))),
               fmaxf(fabsf(san(a.z)), fabsf(san(a.w))));
    if (t < (O_DIM * K_DIM) / 4) {
        float4 w = reinterpret_cast<const float4*>(W)[t];
        md = fmaxf(fmaxf(fabsf(san(w.x)), fabsf(san(w.y))),
                   fmaxf(fabsf(san(w.z)), fabsf(san(w.w))));
    }
    md = fmaxf(md, fabsf(san(b[threadIdx.x])));      // 256 threads cover b exactly
    float2 r = block_max2(mx, md);
    if (threadIdx.x == 0) g_bmax2[blockIdx.x] = r;
}

// ---------------- pass 2: fused quantize + K-split LUT-GEMM + in-kernel epilogue
// grid (8 o-blk, 16 m-blk, KSPLIT=4) = 512 blocks (one full wave). Tile
// 32m x 32o x 64k, 256 threads, 2x2 outputs/thread, 2 instr/MAC inner loop.
// The 4th block to finish a tile sums the 4 int partials and writes floats.
// No block ever waits on the counter -> no deadlock under any scheduling.
__global__ __launch_bounds__(256) void fused_kernel(const float* __restrict__ x,
                                                    const float* __restrict__ W,
                                                    const float* __restrict__ b,
                                                    float* __restrict__ out) {
    __shared__ float s_a[BK][34];   // [k][m]
    __shared__ float s_u[BK][34];   // [k][o]
    __shared__ int   s_neg[32];     // per local-o count of bb<0 in this k-chunk
    __shared__ int   s_last;

    // prologue: finalize global maxima -> sn1, sn2 (all threads)
    float mx = 0.0f, md = 0.0f;
    if (threadIdx.x < RBLK) {
        float2 v = g_bmax2[threadIdx.x];
        mx = v.x; md = v.y;
    }
    float2 r = block_max2(mx, md);
    float sn2 = calc_sn(r.x);
    float sn1 = calc_sn(r.y);

    int m0 = blockIdx.y * 32;
    int o0 = blockIdx.x * 32;
    int kc = blockIdx.z * BK;
    int mm = threadIdx.x >> 3;          // staging row (m for x, o for W)
    int kg = (threadIdx.x & 7) << 3;    // staging k-offset (8 floats)

    // stage + on-the-fly quantize (coalesced LDG.128, transposed STS)
    int negcnt = 0;
    {
        const float4* pa = (const float4*)&x[(m0 + mm) * K_DIM + kc + kg];
        const float4* pw = (const float4*)&W[(o0 + mm) * K_DIM + kc + kg];
        float4 a0 = pa[0], a1 = pa[1];
        float4 w0 = pw[0], w1 = pw[1];
        float av[8] = {a0.x, a0.y, a0.z, a0.w, a1.x, a1.y, a1.z, a1.w};
        float wv[8] = {w0.x, w0.y, w0.z, w0.w, w1.x, w1.y, w1.z, w1.w};
        #pragma unroll
        for (int j = 0; j < 8; j++) {
            s_a[kg + j][mm] = (float)(int)(san(av[j]) * sn2) + THETA;
            int bb = (int)(san(wv[j]) * sn1);
            float us = (float)bb * (1.0f / 32.0f);
            if (bb < 0) { us -= EPSB; negcnt++; }
            s_u[kg + j][mm] = us;
        }
    }
    // per-o negative count over this chunk (8 consecutive lanes share row mm)
    #pragma unroll
    for (int off = 1; off < 8; off <<= 1)
        negcnt += __shfl_xor_sync(0xFFFFFFFFu, negcnt, off);
    if ((threadIdx.x & 7) == 0) s_neg[mm] = negcnt;
    __syncthreads();

    int tx = threadIdx.x & 15;      // o
    int ty = threadIdx.x >> 4;      // m

    unsigned acc00 = 0, acc01 = 0, acc10 = 0, acc11 = 0;

    #pragma unroll 16
    for (int k = 0; k < BK; k++) {
        float2 a2 = *reinterpret_cast<const float2*>(&s_a[k][2 * ty]);
        float2 u2 = *reinterpret_cast<const float2*>(&s_u[k][2 * tx]);
        acc00 += __float_as_uint(__fmaf_rd(a2.x, u2.x, BIGF));
        acc01 += __float_as_uint(__fmaf_rd(a2.x, u2.y, BIGF));
        acc10 += __float_as_uint(__fmaf_rd(a2.y, u2.x, BIGF));
        acc11 += __float_as_uint(__fmaf_rd(a2.y, u2.y, BIGF));
    }

    // exact per-chunk partial: (acc - 64*BIGU mod 2^32) + chunk negative count
    const unsigned C = (unsigned)((unsigned)BK * BIGU);
    int m = m0 + 2 * ty;
    int o = o0 + 2 * tx;
    int n0 = s_neg[2 * tx], n1 = s_neg[2 * tx + 1];
    int* __restrict__ p = g_part[blockIdx.z];
    *reinterpret_cast<int2*>(&p[m * O_DIM + o]) =
        make_int2((int)(acc00 - C) + n0, (int)(acc01 - C) + n1);
    *reinterpret_cast<int2*>(&p[(m + 1) * O_DIM + o]) =
        make_int2((int)(acc10 - C) + n0, (int)(acc11 - C) + n1);

    // ---- last-block-does-epilogue (arrive-and-exit; no waiting) ----
    __syncthreads();                       // all partial stores issued
    int tile = blockIdx.y * (O_DIM / 32) + blockIdx.x;
    if (threadIdx.x == 0) {
        __threadfence();                   // make partials visible chip-wide
        unsigned old = atomicAdd(&g_cnt[tile], 1u);
        s_last = (old == KSPLIT - 1);
        if (old == KSPLIT - 1) g_cnt[tile] = 0u;   // reset for next graph replay
    }
    __syncthreads();
    if (s_last) {
        __threadfence();                   // acquire other blocks' partials
        #pragma unroll
        for (int j = 0; j < 4; j++) {
            int e = threadIdx.x + 256 * j;         // 0..1023 within tile
            int ml = e >> 5, ol = e & 31;
            int idx = (m0 + ml) * O_DIM + o0 + ol;
            int x9 = g_part[0][idx] + g_part[1][idx]
                   + g_part[2][idx] + g_part[3][idx];
            int cc = (int)(san(b[o0 + ol]) * sn1);
            // d = trunc(x9/sn2) + cc ; out = d/sn1 (exact pow-2 ops)
            out[idx] = (float)((int)((float)x9 / sn2) + cc) / sn1;
        }
    }
}

// ---------------- launch ----------------
extern "C" void kernel_launch(void* const* d_in, const int* in_sizes, int n_in,
                              void* d_out, int out_size) {
    (void)in_sizes; (void)n_in; (void)out_size;
    const float* x = (const float*)d_in[0];
    const float* W = (const float*)d_in[1];
    const float* b = (const float*)d_in[2];
    // d_in[3] (lut) unused: lut[i][j] == floor(i*j/32), reproduced exactly by
    // the FFMA.RD magic-floor + raw-bits accumulation.

    reduce_kernel<<<RBLK, 256>>>(x, W, b);
    dim3 grid(O_DIM / 32, M_DIM / 32, KSPLIT);
    fused_kernel<<<grid, 256>>>(x, W, b, (float*)d_out);
}

// round 11
// speedup vs baseline: 1.1978x; 1.0019x over previous
#include <cuda_runtime.h>
#include <cstdint>

#define M_DIM 512
#define K_DIM 256
#define O_DIM 256
#define BK 64
#define KSPLIT 4
#define RBLK 128          /* reduce blocks */

#define BIGF  12582912.0f          /* 1.5 * 2^23 */
#define BIGU  0x4B400000u
#define THETA 0.0009765625f        /* 2^-10 */
#define EPSB  0.000244140625f      /* 2^-12 */

// ---------------- device scratch (no allocations allowed) ----------------
__device__ float2 g_bmax2[RBLK];                  // per-block (max|x|, max(|W|,|b|))
__device__ int    g_part[KSPLIT][M_DIM * O_DIM];  // exact per-chunk partial sums
__device__ unsigned g_cnt[(M_DIM / 32) * (O_DIM / 32)];  // tile arrival counters (=0)

// ---------------- helpers ----------------
__device__ __forceinline__ float san(float v) {
    if (isnan(v)) return 0.0f;
    if (isinf(v)) return 1.0f;
    return v;
}

// sn = 2^floor(log2(floor(32/mx))); argument of log2 is a positive integer.
__device__ __forceinline__ float calc_sn(float mx) {
    if (mx == 0.0f) mx = 1.0f;
    float r = floorf(32.0f / mx);
    return ldexpf(1.0f, ilogbf(r));
}

// block-level max reduce of (mx, md) over 256 threads; result valid in ALL threads
__device__ __forceinline__ float2 block_max2(float mx, float md) {
    __shared__ float2 s_red[8];
    __shared__ float2 s_out;
    #pragma unroll
    for (int off = 16; off; off >>= 1) {
        mx = fmaxf(mx, __shfl_xor_sync(0xFFFFFFFFu, mx, off));
        md = fmaxf(md, __shfl_xor_sync(0xFFFFFFFFu, md, off));
    }
    if ((threadIdx.x & 31) == 0) s_red[threadIdx.x >> 5] = make_float2(mx, md);
    __syncthreads();
    if (threadIdx.x == 0) {
        float2 r = s_red[0];
        #pragma unroll
        for (int w = 1; w < 8; w++) {
            r.x = fmaxf(r.x, s_red[w].x);
            r.y = fmaxf(r.y, s_red[w].y);
        }
        s_out = r;
    }
    __syncthreads();
    return s_out;
}

// ---------------- pass 1: per-block maxima (no atomics, no reset) ----------------
__global__ __launch_bounds__(256) void reduce_kernel(const float* __restrict__ x,
                                                     const float* __restrict__ W,
                                                     const float* __restrict__ b) {
    int t = blockIdx.x * 256 + threadIdx.x;          // 0..32767
    float mx = 0.0f, md = 0.0f;
    float4 a = reinterpret_cast<const float4*>(x)[t];            // covers M*K exactly
    mx = fmaxf(fmaxf(fabsf(san(a.x)), fabsf(san(a.y))),
               fmaxf(fabsf(san(a.z)), fabsf(san(a.w))));
    if (t < (O_DIM * K_DIM) / 4) {
        float4 w = reinterpret_cast<const float4*>(W)[t];
        md = fmaxf(fmaxf(fabsf(san(w.x)), fabsf(san(w.y))),
                   fmaxf(fabsf(san(w.z)), fabsf(san(w.w))));
    }
    md = fmaxf(md, fabsf(san(b[threadIdx.x])));      // 256 threads cover b exactly
    float2 r = block_max2(mx, md);
    if (threadIdx.x == 0) g_bmax2[blockIdx.x] = r;
}

// ---------------- pass 2: fused quantize + K-split LUT-GEMM + in-kernel epilogue
// grid (8 o-blk, 16 m-blk, KSPLIT=4) = 512 blocks. Tile 32m x 32o x 64k,
// 256 threads, 2x2 outputs/thread. Inner loop: the accumulator IS the FFMA
// addend -> 1 FFMA.RD per MAC, no integer adds (1.5 instr/MAC).
__global__ __launch_bounds__(256) void fused_kernel(const float* __restrict__ x,
                                                    const float* __restrict__ W,
                                                    const float* __restrict__ b,
                                                    float* __restrict__ out) {
    __shared__ float s_a[BK][34];   // [k][m]
    __shared__ float s_u[BK][34];   // [k][o]
    __shared__ int   s_neg[32];     // per local-o count of bb<0 in this k-chunk
    __shared__ int   s_last;

    // prologue: finalize global maxima -> sn1, sn2 (all threads)
    float mx = 0.0f, md = 0.0f;
    if (threadIdx.x < RBLK) {
        float2 v = g_bmax2[threadIdx.x];
        mx = v.x; md = v.y;
    }
    float2 r = block_max2(mx, md);
    float sn2 = calc_sn(r.x);
    float sn1 = calc_sn(r.y);

    int m0 = blockIdx.y * 32;
    int o0 = blockIdx.x * 32;
    int kc = blockIdx.z * BK;
    int mm = threadIdx.x >> 3;          // staging row (m for x, o for W)
    int kg = (threadIdx.x & 7) << 3;    // staging k-offset (8 floats)

    // stage + on-the-fly quantize (coalesced LDG.128, transposed STS)
    int negcnt = 0;
    {
        const float4* pa = (const float4*)&x[(m0 + mm) * K_DIM + kc + kg];
        const float4* pw = (const float4*)&W[(o0 + mm) * K_DIM + kc + kg];
        float4 a0 = pa[0], a1 = pa[1];
        float4 w0 = pw[0], w1 = pw[1];
        float av[8] = {a0.x, a0.y, a0.z, a0.w, a1.x, a1.y, a1.z, a1.w};
        float wv[8] = {w0.x, w0.y, w0.z, w0.w, w1.x, w1.y, w1.z, w1.w};
        #pragma unroll
        for (int j = 0; j < 8; j++) {
            s_a[kg + j][mm] = (float)(int)(san(av[j]) * sn2) + THETA;
            int bb = (int)(san(wv[j]) * sn1);
            float us = (float)bb * (1.0f / 32.0f);
            if (bb < 0) { us -= EPSB; negcnt++; }
            s_u[kg + j][mm] = us;
        }
    }
    // per-o negative count over this chunk (8 consecutive lanes share row mm)
    #pragma unroll
    for (int off = 1; off < 8; off <<= 1)
        negcnt += __shfl_xor_sync(0xFFFFFFFFu, negcnt, off);
    if ((threadIdx.x & 7) == 0) s_neg[mm] = negcnt;
    __syncthreads();

    int tx = threadIdx.x & 15;      // o
    int ty = threadIdx.x >> 4;      // m

    // float accumulator chains: integer-valued, stay in [2^23, 2^24) since
    // |running sum| <= 64*961 << 2^22. Each FFMA.RD adds exactly floor(a*u).
    float f00 = BIGF, f01 = BIGF, f10 = BIGF, f11 = BIGF;

    #pragma unroll 16
    for (int k = 0; k < BK; k++) {
        float2 a2 = *reinterpret_cast<const float2*>(&s_a[k][2 * ty]);
        float2 u2 = *reinterpret_cast<const float2*>(&s_u[k][2 * tx]);
        f00 = __fmaf_rd(a2.x, u2.x, f00);
        f01 = __fmaf_rd(a2.x, u2.y, f01);
        f10 = __fmaf_rd(a2.y, u2.x, f10);
        f11 = __fmaf_rd(a2.y, u2.y, f11);
    }

    // exact per-chunk partial: S = bits(f) - BIGU, plus chunk negative count
    int m = m0 + 2 * ty;
    int o = o0 + 2 * tx;
    int n0 = s_neg[2 * tx], n1 = s_neg[2 * tx + 1];
    int* __restrict__ p = g_part[blockIdx.z];
    *reinterpret_cast<int2*>(&p[m * O_DIM + o]) =
        make_int2((int)(__float_as_uint(f00) - BIGU) + n0,
                  (int)(__float_as_uint(f01) - BIGU) + n1);
    *reinterpret_cast<int2*>(&p[(m + 1) * O_DIM + o]) =
        make_int2((int)(__float_as_uint(f10) - BIGU) + n0,
                  (int)(__float_as_uint(f11) - BIGU) + n1);

    // ---- last-block-does-epilogue (arrive-and-exit; no waiting) ----
    __syncthreads();                       // all partial stores issued
    int tile = blockIdx.y * (O_DIM / 32) + blockIdx.x;
    if (threadIdx.x == 0) {
        __threadfence();                   // make partials visible chip-wide
        unsigned old = atomicAdd(&g_cnt[tile], 1u);
        s_last = (old == KSPLIT - 1);
        if (old == KSPLIT - 1) g_cnt[tile] = 0u;   // reset for next graph replay
    }
    __syncthreads();
    if (s_last) {
        __threadfence();                   // acquire other blocks' partials
        #pragma unroll
        for (int j = 0; j < 4; j++) {
            int e = threadIdx.x + 256 * j;         // 0..1023 within tile
            int ml = e >> 5, ol = e & 31;
            int idx = (m0 + ml) * O_DIM + o0 + ol;
            int x9 = g_part[0][idx] + g_part[1][idx]
                   + g_part[2][idx] + g_part[3][idx];
            int cc = (int)(san(b[o0 + ol]) * sn1);
            // d = trunc(x9/sn2) + cc ; out = d/sn1 (exact pow-2 ops)
            out[idx] = (float)((int)((float)x9 / sn2) + cc) / sn1;
        }
    }
}

// ---------------- launch ----------------
extern "C" void kernel_launch(void* const* d_in, const int* in_sizes, int n_in,
                              void* d_out, int out_size) {
    (void)in_sizes; (void)n_in; (void)out_size;
    const float* x = (const float*)d_in[0];
    const float* W = (const float*)d_in[1];
    const float* b = (const float*)d_in[2];
    // d_in[3] (lut) unused: lut[i][j] == floor(i*j/32), reproduced exactly by
    // chained FFMA.RD magic-floor accumulation.

    reduce_kernel<<<RBLK, 256>>>(x, W, b);
    dim3 grid(O_DIM / 32, M_DIM / 32, KSPLIT);
    fused_kernel<<<grid, 256>>>(x, W, b, (float*)d_out);
}

// round 13
// speedup vs baseline: 1.2022x; 1.0037x over previous
#include <cuda_runtime.h>
#include <cstdint>

#define M_DIM 512
#define K_DIM 256
#define O_DIM 256
#define BK 64
#define KSPLIT 4
#define RBLK 128          /* reduce blocks */

#define BIGF  12582912.0f          /* 1.5 * 2^23 */
#define BIGU  0x4B400000u
#define THETA 0.0009765625f        /* 2^-10 */
#define EPSB  0.000244140625f      /* 2^-12 */

// ---------------- device scratch (no allocations allowed) ----------------
__device__ float2 g_bmax2[RBLK];                  // per-block (max|x|, max(|W|,|b|))
__device__ unsigned g_rcnt;                       // reduce arrival counter (=0)
__device__ __align__(16) float g_sn[4];           // {sn1, sn2, 1/sn1, 1/sn2}
__device__ int    g_part[KSPLIT][M_DIM * O_DIM];  // exact per-chunk partial sums
__device__ unsigned g_cnt[(M_DIM / 32) * (O_DIM / 32)];  // tile arrival counters (=0)

// ---------------- helpers ----------------
__device__ __forceinline__ float san(float v) {
    if (isnan(v)) return 0.0f;
    if (isinf(v)) return 1.0f;
    return v;
}

// sn = 2^floor(log2(floor(32/mx))); argument of log2 is a positive integer.
__device__ __forceinline__ float calc_sn(float mx) {
    if (mx == 0.0f) mx = 1.0f;
    float r = floorf(32.0f / mx);
    return ldexpf(1.0f, ilogbf(r));
}

// block-level max reduce of (mx, md) over 256 threads; result valid in ALL threads
__device__ __forceinline__ float2 block_max2(float mx, float md) {
    __shared__ float2 s_red[8];
    __shared__ float2 s_out;
    #pragma unroll
    for (int off = 16; off; off >>= 1) {
        mx = fmaxf(mx, __shfl_xor_sync(0xFFFFFFFFu, mx, off));
        md = fmaxf(md, __shfl_xor_sync(0xFFFFFFFFu, md, off));
    }
    if ((threadIdx.x & 31) == 0) s_red[threadIdx.x >> 5] = make_float2(mx, md);
    __syncthreads();
    if (threadIdx.x == 0) {
        float2 r = s_red[0];
        #pragma unroll
        for (int w = 1; w < 8; w++) {
            r.x = fmaxf(r.x, s_red[w].x);
            r.y = fmaxf(r.y, s_red[w].y);
        }
        s_out = r;
    }
    __syncthreads();
    return s_out;
}

// ---------------- pass 1: maxima + last-block sn finalization ----------------
__global__ __launch_bounds__(256) void reduce_kernel(const float* __restrict__ x,
                                                     const float* __restrict__ W,
                                                     const float* __restrict__ b) {
    __shared__ int s_fin;
    int t = blockIdx.x * 256 + threadIdx.x;          // 0..32767
    float mx = 0.0f, md = 0.0f;
    float4 a = reinterpret_cast<const float4*>(x)[t];            // covers M*K exactly
    mx = fmaxf(fmaxf(fabsf(san(a.x)), fabsf(san(a.y))),
               fmaxf(fabsf(san(a.z)), fabsf(san(a.w))));
    if (t < (O_DIM * K_DIM) / 4) {
        float4 w = reinterpret_cast<const float4*>(W)[t];
        md = fmaxf(fmaxf(fabsf(san(w.x)), fabsf(san(w.y))),
                   fmaxf(fabsf(san(w.z)), fabsf(san(w.w))));
    }
    md = fmaxf(md, fabsf(san(b[threadIdx.x])));      // 256 threads cover b exactly
    float2 r = block_max2(mx, md);
    if (threadIdx.x == 0) {
        g_bmax2[blockIdx.x] = r;
        __threadfence();
        unsigned old = atomicAdd(&g_rcnt, 1u);
        s_fin = (old == RBLK - 1);
        if (old == RBLK - 1) g_rcnt = 0u;            // reset for next graph replay
    }
    __syncthreads();
    if (s_fin) {                                     // last block finalizes sn
        __threadfence();
        float mx2 = 0.0f, md2 = 0.0f;
        if (threadIdx.x < RBLK) {
            float2 v = g_bmax2[threadIdx.x];
            mx2 = v.x; md2 = v.y;
        }
        float2 r2 = block_max2(mx2, md2);
        if (threadIdx.x == 0) {
            float sn2 = calc_sn(r2.x);
            float sn1 = calc_sn(r2.y);
            g_sn[0] = sn1; g_sn[1] = sn2;
            g_sn[2] = 1.0f / sn1; g_sn[3] = 1.0f / sn2;   // exact (pow-2)
        }
    }
}

// ---------------- pass 2: fused quantize + K-split LUT-GEMM + in-kernel epilogue
// grid (8 o-blk, 16 m-blk, KSPLIT=4) = 512 blocks. Tile 32m x 32o x 64k,
// 256 threads, 2x2 outputs/thread, 1 FFMA.RD per MAC.
// Staging quantize is conversion-free: floor via FADD.RD magic on the
// RN-rounded product (bit-identical to JAX trunc(RN(v*sn)) for v>=0 / via |.|).
__global__ __launch_bounds__(256) void fused_kernel(const float* __restrict__ x,
                                                    const float* __restrict__ W,
                                                    const float* __restrict__ b,
                                                    float* __restrict__ out) {
    __shared__ float s_a[BK][34];   // [k][m]
    __shared__ float s_u[BK][34];   // [k][o]
    __shared__ int   s_neg[32];     // per local-o count of bb<0 in this k-chunk
    __shared__ int   s_last;

    // prologue: one uniform load (sn finalized by reduce's last block)
    float4 sn4 = *reinterpret_cast<const float4*>(g_sn);
    float sn1 = sn4.x, sn2 = sn4.y, inv1 = sn4.z, inv2 = sn4.w;

    int m0 = blockIdx.y * 32;
    int o0 = blockIdx.x * 32;
    int kc = blockIdx.z * BK;
    int mm = threadIdx.x >> 3;          // staging row (m for x, o for W)
    int kg = (threadIdx.x & 7) << 3;    // staging k-offset (8 floats)

    // stage + conversion-free quantize (coalesced LDG.128, transposed STS)
    int negcnt = 0;
    {
        const float4* pa = (const float4*)&x[(m0 + mm) * K_DIM + kc + kg];
        const float4* pw = (const float4*)&W[(o0 + mm) * K_DIM + kc + kg];
        float4 a0 = pa[0], a1 = pa[1];
        float4 w0 = pw[0], w1 = pw[1];
        float av[8] = {a0.x, a0.y, a0.z, a0.w, a1.x, a1.y, a1.z, a1.w};
        float wv[8] = {w0.x, w0.y, w0.z, w0.w, w1.x, w1.y, w1.z, w1.w};
        #pragma unroll
        for (int j = 0; j < 8; j++) {
            // x: t = RN(x*sn2) >= 0 ; floor(t) exactly via FADD.RD magic
            float t  = san(av[j]) * sn2;
            float fl = __fadd_rd(t, BIGF) - BIGF;
            s_a[kg + j][mm] = fl + THETA;
            // W: tw = RN(w*sn1) ; |bb| = floor(|tw|) ; sign + EPSB via selects
            float tw = san(wv[j]) * sn1;
            float ab = __fadd_rd(fabsf(tw), BIGF) - BIGF;
            bool  isneg = (tw < 0.0f) && (ab > 0.0f);
            float us = ab * (1.0f / 32.0f);
            us = (tw < 0.0f) ? -us : us;
            if (isneg) { us -= EPSB; negcnt++; }
            s_u[kg + j][mm] = us;
        }
    }
    // per-o negative count over this chunk (8 consecutive lanes share row mm)
    #pragma unroll
    for (int off = 1; off < 8; off <<= 1)
        negcnt += __shfl_xor_sync(0xFFFFFFFFu, negcnt, off);
    if ((threadIdx.x & 7) == 0) s_neg[mm] = negcnt;
    __syncthreads();

    int tx = threadIdx.x & 15;      // o
    int ty = threadIdx.x >> 4;      // m

    // float accumulator chains: integer-valued, stay in [2^23, 2^24).
    // Each FFMA.RD adds exactly floor(a'*u') to the chain.
    float f00 = BIGF, f01 = BIGF, f10 = BIGF, f11 = BIGF;

    #pragma unroll 16
    for (int k = 0; k < BK; k++) {
        float2 a2 = *reinterpret_cast<const float2*>(&s_a[k][2 * ty]);
        float2 u2 = *reinterpret_cast<const float2*>(&s_u[k][2 * tx]);
        f00 = __fmaf_rd(a2.x, u2.x, f00);
        f01 = __fmaf_rd(a2.x, u2.y, f01);
        f10 = __fmaf_rd(a2.y, u2.x, f10);
        f11 = __fmaf_rd(a2.y, u2.y, f11);
    }

    // exact per-chunk partial: S = bits(f) - BIGU, plus chunk negative count
    int m = m0 + 2 * ty;
    int o = o0 + 2 * tx;
    int n0 = s_neg[2 * tx], n1 = s_neg[2 * tx + 1];
    int* __restrict__ p = g_part[blockIdx.z];
    *reinterpret_cast<int2*>(&p[m * O_DIM + o]) =
        make_int2((int)(__float_as_uint(f00) - BIGU) + n0,
                  (int)(__float_as_uint(f01) - BIGU) + n1);
    *reinterpret_cast<int2*>(&p[(m + 1) * O_DIM + o]) =
        make_int2((int)(__float_as_uint(f10) - BIGU) + n0,
                  (int)(__float_as_uint(f11) - BIGU) + n1);

    // ---- last-block-does-epilogue (arrive-and-exit; no waiting) ----
    __syncthreads();                       // all partial stores issued
    int tile = blockIdx.y * (O_DIM / 32) + blockIdx.x;
    if (threadIdx.x == 0) {
        __threadfence();                   // make partials visible chip-wide
        unsigned old = atomicAdd(&g_cnt[tile], 1u);
        s_last = (old == KSPLIT - 1);
        if (old == KSPLIT - 1) g_cnt[tile] = 0u;   // reset for next graph replay
    }
    __syncthreads();
    if (s_last) {
        __threadfence();                   // acquire other blocks' partials
        #pragma unroll
        for (int j = 0; j < 4; j++) {
            int e = threadIdx.x + 256 * j;         // 0..1023 within tile
            int ml = e >> 5, ol = e & 31;
            int idx = (m0 + ml) * O_DIM + o0 + ol;
            int x9 = g_part[0][idx] + g_part[1][idx]
                   + g_part[2][idx] + g_part[3][idx];
            int cc = (int)(san(b[o0 + ol]) * sn1);
            // d = trunc(x9 * 1/sn2) + cc ; out = d * 1/sn1 (all exact pow-2)
            int d = (int)((float)x9 * inv2) + cc;
            out[idx] = (float)d * inv1;
        }
    }
}

// ---------------- launch ----------------
extern "C" void kernel_launch(void* const* d_in, const int* in_sizes, int n_in,
                              void* d_out, int out_size) {
    (void)in_sizes; (void)n_in; (void)out_size;
    const float* x = (const float*)d_in[0];
    const float* W = (const float*)d_in[1];
    const float* b = (const float*)d_in[2];
    // d_in[3] (lut) unused: lut[i][j] == floor(i*j/32), reproduced exactly by
    // chained FFMA.RD magic-floor accumulation.

    reduce_kernel<<<RBLK, 256>>>(x, W, b);
    dim3 grid(O_DIM / 32, M_DIM / 32, KSPLIT);
    fused_kernel<<<grid, 256>>>(x, W, b, (float*)d_out);
}